// round 3
// baseline (speedup 1.0000x reference)
#include <cuda_runtime.h>
#include <math.h>
#include <stdint.h>

#define NB 256
#define S  4096
#define FO 8
#define NM 64
#define FM 6
#define EPSF 1e-5f

#define PC    8        // CTAs per instance = cluster size
#define PT    512      // threads per CTA
#define CHUNK 8192     // float4 per proc CTA (128 KB)
#define OCH   8192     // float4 per opes instance (128 KB)

__device__ __forceinline__ float warp_sum(float v) {
#pragma unroll
    for (int o = 16; o > 0; o >>= 1) v += __shfl_down_sync(0xffffffffu, v, o);
    return v;
}

__device__ __forceinline__ uint32_t smem_u32(const void* p) {
    return (uint32_t)__cvta_generic_to_shared((void*)p);
}

__device__ __forceinline__ void dsmem_st_f32(uint32_t laddr, uint32_t rank, float v) {
    uint32_t r;
    asm volatile("mapa.shared::cluster.u32 %0, %1, %2;" : "=r"(r) : "r"(laddr), "r"(rank));
    asm volatile("st.shared::cluster.f32 [%0], %1;" :: "r"(r), "f"(v));
}

__device__ __forceinline__ void cluster_sync_() {
    asm volatile("barrier.cluster.arrive.aligned;" ::: "memory");
    asm volatile("barrier.cluster.wait.aligned;" ::: "memory");
}

// ===================== proc_time: single-pass via cluster + SMEM =====================
// 8 CTAs per instance; each holds 128 KB chunk in SMEM across the stats exchange.
__global__ void __cluster_dims__(PC, 1, 1) __launch_bounds__(PT, 1)
proc_k(const float4* __restrict__ pt, float4* __restrict__ out) {
    extern __shared__ char dyn[];
    float*  stats = (float*)dyn;              // 8 ranks x 4 floats (pad) = 128 B
    float4* data  = (float4*)(dyn + 128);     // 8192 float4

    int b    = blockIdx.x >> 3;
    int rank = blockIdx.x & 7;
    size_t base = (size_t)b * (S * NM / 4) + (size_t)rank * CHUNK;
    const float4* src = pt + base;
    float4*       dst = out + base;

    // pass 1: stream in -> SMEM, accumulate
    float s = 0.f, ss = 0.f, c = 0.f;
#pragma unroll 4
    for (int i = threadIdx.x; i < CHUNK; i += PT) {
        float4 v = __ldcs(src + i);
        data[i] = v;
        s  += (v.x + v.y) + (v.z + v.w);
        ss += (v.x * v.x + v.y * v.y) + (v.z * v.z + v.w * v.w);
        c  += (float)((v.x != 0.f) + (v.y != 0.f) + (v.z != 0.f) + (v.w != 0.f));
    }

    // block reduce
    __shared__ float red[3][16];
    __shared__ float bc[3];
    int lane = threadIdx.x & 31, w = threadIdx.x >> 5;
    s = warp_sum(s); ss = warp_sum(ss); c = warp_sum(c);
    if (lane == 0) { red[0][w] = s; red[1][w] = ss; red[2][w] = c; }
    __syncthreads();
    if (threadIdx.x == 0) {
        float a = 0.f, q = 0.f, cc = 0.f;
#pragma unroll
        for (int i = 0; i < 16; i++) { a += red[0][i]; q += red[1][i]; cc += red[2][i]; }
        bc[0] = a; bc[1] = q; bc[2] = cc;
    }
    __syncthreads();

    // broadcast my partials into every cluster CTA's stats[rank]
    if (threadIdx.x < PC) {
        uint32_t a0 = smem_u32(&stats[rank * 4]);
        dsmem_st_f32(a0 + 0, threadIdx.x, bc[0]);
        dsmem_st_f32(a0 + 4, threadIdx.x, bc[1]);
        dsmem_st_f32(a0 + 8, threadIdx.x, bc[2]);
    }
    cluster_sync_();   // release/acquire: peer DSMEM stores visible after this

    float St = 0.f, SSt = 0.f, Ct = 0.f;
#pragma unroll
    for (int r2 = 0; r2 < PC; r2++) {
        St += stats[r2 * 4]; SSt += stats[r2 * 4 + 1]; Ct += stats[r2 * 4 + 2];
    }
    float m   = St / Ct;
    float var = (SSt - St * St / Ct) / (Ct - 1.f);
    float rr  = 1.f / (sqrtf(var) + EPSF);

    // pass 2: normalize from SMEM, stream out
#pragma unroll 4
    for (int i = threadIdx.x; i < CHUNK; i += PT) {
        float4 v = data[i];
        float4 o;
        o.x = (v.x != 0.f) ? (v.x - m) * rr : 0.f;
        o.y = (v.y != 0.f) ? (v.y - m) * rr : 0.f;
        o.z = (v.z != 0.f) ? (v.z - m) * rr : 0.f;
        o.w = (v.w != 0.f) ? (v.w - m) * rr : 0.f;
        __stcs(dst + i, o);
    }
}

// ===================== opes (ragged mask) + mas: fused single-pass =====================
__global__ void __launch_bounds__(PT, 1)
opes_k(const float* __restrict__ opes, const float* __restrict__ mas,
       const int* __restrict__ nums,
       float* __restrict__ out_opes, float* __restrict__ out_mas) {
    extern __shared__ char dyn[];
    float4* data = (float4*)dyn;                    // 8192 float4 = 128 KB

    __shared__ float4 smas4[NM * FM / 4];           // 96 float4
    __shared__ float4 shs[16][2], shq[16][2];
    __shared__ float  M[FO], R[FO], mM[FM], mR[FM];

    int b = blockIdx.x;
    int n = nums[b];
    const float4* src = (const float4*)(opes + (size_t)b * S * FO);

    // load opes -> SMEM with masked accumulation.
    // stride PT=512 is even -> each thread's float4 index parity is fixed:
    // even tid => features 0-3, odd tid => features 4-7.
    float4 s4 = make_float4(0.f, 0.f, 0.f, 0.f);
    float4 q4 = make_float4(0.f, 0.f, 0.f, 0.f);
#pragma unroll 4
    for (int i = threadIdx.x; i < OCH; i += PT) {
        float4 v = __ldcs(src + i);
        data[i] = v;
        if ((i >> 1) < n) {
            s4.x += v.x; s4.y += v.y; s4.z += v.z; s4.w += v.w;
            q4.x += v.x * v.x; q4.y += v.y * v.y; q4.z += v.z * v.z; q4.w += v.w * v.w;
        }
    }
    // mas -> SMEM (cooperative, before first sync)
    if (threadIdx.x < NM * FM / 4) {
        const float4* msrc = (const float4*)(mas + (size_t)b * NM * FM);
        smas4[threadIdx.x] = msrc[threadIdx.x];
    }

    // warp reduce preserving lane parity (features split even/odd lanes)
#pragma unroll
    for (int off = 2; off < 32; off <<= 1) {
        s4.x += __shfl_xor_sync(0xffffffffu, s4.x, off);
        s4.y += __shfl_xor_sync(0xffffffffu, s4.y, off);
        s4.z += __shfl_xor_sync(0xffffffffu, s4.z, off);
        s4.w += __shfl_xor_sync(0xffffffffu, s4.w, off);
        q4.x += __shfl_xor_sync(0xffffffffu, q4.x, off);
        q4.y += __shfl_xor_sync(0xffffffffu, q4.y, off);
        q4.z += __shfl_xor_sync(0xffffffffu, q4.z, off);
        q4.w += __shfl_xor_sync(0xffffffffu, q4.w, off);
    }
    int lane = threadIdx.x & 31, w = threadIdx.x >> 5;
    if (lane < 2) { shs[w][lane] = s4; shq[w][lane] = q4; }
    __syncthreads();

    if (threadIdx.x < 32) {
        int p = threadIdx.x & 1, ww = threadIdx.x >> 1;   // tid = ww*2 + p
        float4 a = shs[ww][p], q = shq[ww][p];
#pragma unroll
        for (int off = 2; off < 32; off <<= 1) {
            a.x += __shfl_xor_sync(0xffffffffu, a.x, off);
            a.y += __shfl_xor_sync(0xffffffffu, a.y, off);
            a.z += __shfl_xor_sync(0xffffffffu, a.z, off);
            a.w += __shfl_xor_sync(0xffffffffu, a.w, off);
            q.x += __shfl_xor_sync(0xffffffffu, q.x, off);
            q.y += __shfl_xor_sync(0xffffffffu, q.y, off);
            q.z += __shfl_xor_sync(0xffffffffu, q.z, off);
            q.w += __shfl_xor_sync(0xffffffffu, q.w, off);
        }
        if (threadIdx.x < 2) {
            float fn = (float)n;
            int f0 = p * 4;
            float* sa = &a.x; float* qa = &q.x;
#pragma unroll
            for (int k = 0; k < 4; k++) {
                float mean = sa[k] / fn;
                float var  = (qa[k] - sa[k] * sa[k] / fn) / (fn - 1.f);
                M[f0 + k] = mean;
                R[f0 + k] = 1.f / (sqrtf(var) + EPSF);
            }
        }
    }
    // mas stats on warp 2 (smas4 complete after the sync above)
    if (threadIdx.x >= 64 && threadIdx.x < 64 + FM) {
        int f = threadIdx.x - 64;
        const float* sm = (const float*)smas4;
        float ts = 0.f, tq = 0.f;
#pragma unroll
        for (int r2 = 0; r2 < NM; r2++) { float x = sm[r2 * FM + f]; ts += x; tq += x * x; }
        float fm   = (float)NM;
        float mean = ts / fm;
        float var  = (tq - ts * ts / fm) / (fm - 1.f);
        mM[f] = mean;
        mR[f] = 1.f / (sqrtf(var) + EPSF);
    }
    __syncthreads();

    // normalize opes from SMEM, stream out
    float4* dsto = ((float4*)out_opes) + (size_t)b * OCH;
#pragma unroll 4
    for (int i = threadIdx.x; i < OCH; i += PT) {
        float4 v = data[i];
        int g = (i & 1) * 4;
        float4 o;
        o.x = (v.x - M[g + 0]) * R[g + 0];
        o.y = (v.y - M[g + 1]) * R[g + 1];
        o.z = (v.z - M[g + 2]) * R[g + 2];
        o.w = (v.w - M[g + 3]) * R[g + 3];
        __stcs(dsto + i, o);
    }
    // normalize mas
    if (threadIdx.x < NM * FM) {
        int f = threadIdx.x % FM;
        float x = ((const float*)smas4)[threadIdx.x];
        __stcs(out_mas + (size_t)b * NM * FM + threadIdx.x, (x - mM[f]) * mR[f]);
    }
}

extern "C" void kernel_launch(void* const* d_in, const int* in_sizes, int n_in,
                              void* d_out, int out_size) {
    const float* raw_opes = (const float*)d_in[0];
    const float* raw_mas  = (const float*)d_in[1];
    const float* proc     = (const float*)d_in[2];
    const int*   nums     = (const int*)d_in[3];

    float* out_opes = (float*)d_out;
    float* out_mas  = out_opes + (size_t)NB * S * FO;
    float* out_proc = out_mas  + (size_t)NB * NM * FM;

    cudaFuncSetAttribute(proc_k, cudaFuncAttributeMaxDynamicSharedMemorySize, 128 + CHUNK * 16);
    cudaFuncSetAttribute(opes_k, cudaFuncAttributeMaxDynamicSharedMemorySize, OCH * 16);

    proc_k<<<NB * PC, PT, 128 + CHUNK * 16>>>((const float4*)proc, (float4*)out_proc);
    opes_k<<<NB, PT, OCH * 16>>>(raw_opes, raw_mas, nums, out_opes, out_mas);
}